// round 2
// baseline (speedup 1.0000x reference)
#include <cuda_runtime.h>
#include <math.h>

#define H 128
#define C 64
#define MAXN 100000

// Scratch (allocation-free rule: __device__ globals)
__device__ float g_hA[(size_t)MAXN * H];
__device__ float g_hB[(size_t)MAXN * H];
__device__ float g_scale[6 * H];
__device__ float g_bias[6 * H];

// ---------------------------------------------------------------------------
// Fold BN into per-column scale/bias:  y = (xW+b -m)*g*rsqrt(v+eps)+beta
//   => y = (xW)*scale + bias2,  scale=g*rsqrt(v+eps), bias2=(b-m)*scale+beta
// ---------------------------------------------------------------------------
__global__ void setup_kernel(const float* __restrict__ conv_b,
                             const float* __restrict__ bn_g,
                             const float* __restrict__ bn_b,
                             const float* __restrict__ bn_m,
                             const float* __restrict__ bn_v) {
    int i = blockIdx.x * blockDim.x + threadIdx.x;
    if (i >= 6 * H) return;
    float s = bn_g[i] * rsqrtf(bn_v[i] + 1e-5f);
    g_scale[i] = s;
    g_bias[i]  = (conv_b[i] - bn_m[i]) * s + bn_b[i];
}

// ---------------------------------------------------------------------------
// Edge scatter-add: buf[dst] += h[src], 8 threads per edge, float4 vector REDs
// ---------------------------------------------------------------------------
__device__ __forceinline__ void red_add_v4(float* p, float4 v) {
    asm volatile("red.global.add.v4.f32 [%0], {%1, %2, %3, %4};"
                 :: "l"(p), "f"(v.x), "f"(v.y), "f"(v.z), "f"(v.w)
                 : "memory");
}

__global__ void __launch_bounds__(256) scatter_kernel(
        const float* __restrict__ h, const int* __restrict__ src,
        const int* __restrict__ dst, float* __restrict__ buf, int nE) {
    int i = blockIdx.x * blockDim.x + threadIdx.x;
    if (i >= nE * 8) return;
    int e = i >> 3;
    int c = (i & 7) << 4;               // 16-float chunk per thread
    int s = src[e], d = dst[e];
    const float4* hp = (const float4*)(h + (size_t)s * H + c);
    float* bp = buf + (size_t)d * H + c;
#pragma unroll
    for (int q = 0; q < 4; q++) {
        float4 v = hp[q];
        red_add_v4(bp + q * 4, v);
    }
}

// ---------------------------------------------------------------------------
// Fused Linear(H->H) + folded-BN affine + ReLU.
// SGEMM: 128x128 block tile, BK=8, 8x8 per-thread register tile, 256 threads.
// A: [n,128] row-major, W: [128,128] row-major (k-major).
// ---------------------------------------------------------------------------
__global__ void __launch_bounds__(256) mlp_kernel(
        const float* __restrict__ A, const float* __restrict__ W,
        const float* __restrict__ scale, const float* __restrict__ bias,
        float* __restrict__ out, int n) {
    __shared__ float As[8][132];   // padded to dodge 2-way store conflicts
    __shared__ float Bs[8][132];

    const int tid = threadIdx.x;
    const int tx = tid & 15;       // 16 col-groups * 8 cols
    const int ty = tid >> 4;       // 16 row-groups * 8 rows
    const int block_row = blockIdx.x * 128;

    // A-tile load mapping: 128 rows x 8 k, one float4 per thread
    const int arow  = tid >> 1;
    const int acol4 = (tid & 1) * 4;
    // W-tile load mapping: 8 k-rows x 128 cols, one float4 per thread
    const int wrow  = tid >> 5;
    const int wcol4 = (tid & 31) * 4;

    float acc[8][8];
#pragma unroll
    for (int i = 0; i < 8; i++)
#pragma unroll
        for (int j = 0; j < 8; j++) acc[i][j] = 0.f;

    for (int kk = 0; kk < H; kk += 8) {
        int gr = block_row + arow;
        float4 av = make_float4(0.f, 0.f, 0.f, 0.f);
        if (gr < n) av = *(const float4*)(A + (size_t)gr * H + kk + acol4);
        As[acol4 + 0][arow] = av.x;
        As[acol4 + 1][arow] = av.y;
        As[acol4 + 2][arow] = av.z;
        As[acol4 + 3][arow] = av.w;

        float4 wv = *(const float4*)(W + (size_t)(kk + wrow) * H + wcol4);
        *(float4*)&Bs[wrow][wcol4] = wv;
        __syncthreads();

#pragma unroll
        for (int k = 0; k < 8; k++) {
            float4 a0 = *(const float4*)&As[k][ty * 8];
            float4 a1 = *(const float4*)&As[k][ty * 8 + 4];
            float4 b0 = *(const float4*)&Bs[k][tx * 8];
            float4 b1 = *(const float4*)&Bs[k][tx * 8 + 4];
            float a[8] = {a0.x, a0.y, a0.z, a0.w, a1.x, a1.y, a1.z, a1.w};
            float b[8] = {b0.x, b0.y, b0.z, b0.w, b1.x, b1.y, b1.z, b1.w};
#pragma unroll
            for (int i = 0; i < 8; i++)
#pragma unroll
                for (int j = 0; j < 8; j++) acc[i][j] += a[i] * b[j];
        }
        __syncthreads();
    }

    // epilogue: affine + relu
#pragma unroll
    for (int i = 0; i < 8; i++) {
        int gr = block_row + ty * 8 + i;
        if (gr < n) {
#pragma unroll
            for (int j = 0; j < 8; j += 4) {
                int cc = tx * 8 + j;
                float4 v;
                v.x = fmaxf(fmaf(acc[i][j + 0], scale[cc + 0], bias[cc + 0]), 0.f);
                v.y = fmaxf(fmaf(acc[i][j + 1], scale[cc + 1], bias[cc + 1]), 0.f);
                v.z = fmaxf(fmaf(acc[i][j + 2], scale[cc + 2], bias[cc + 2]), 0.f);
                v.w = fmaxf(fmaf(acc[i][j + 3], scale[cc + 3], bias[cc + 3]), 0.f);
                *(float4*)(out + (size_t)gr * H + cc) = v;
            }
        }
    }
}

// ---------------------------------------------------------------------------
// FC: [n,128] @ [128,64] + bias -> logits (no relu). 128x64 tile, 8x4/thread.
// ---------------------------------------------------------------------------
__global__ void __launch_bounds__(256) fc_kernel(
        const float* __restrict__ A, const float* __restrict__ W,
        const float* __restrict__ b, float* __restrict__ out, int n) {
    __shared__ float As[8][132];
    __shared__ float Bs[8][68];

    const int tid = threadIdx.x;
    const int tx = tid & 15;       // 16 groups * 4 cols = 64
    const int ty = tid >> 4;       // 16 groups * 8 rows = 128
    const int block_row = blockIdx.x * 128;

    const int arow  = tid >> 1;
    const int acol4 = (tid & 1) * 4;
    const int wrow  = tid >> 4;          // 0..15 (only tid<128 used)
    const int wcol4 = (tid & 15) * 4;

    float acc[8][4];
#pragma unroll
    for (int i = 0; i < 8; i++)
#pragma unroll
        for (int j = 0; j < 4; j++) acc[i][j] = 0.f;

    for (int kk = 0; kk < H; kk += 8) {
        int gr = block_row + arow;
        float4 av = make_float4(0.f, 0.f, 0.f, 0.f);
        if (gr < n) av = *(const float4*)(A + (size_t)gr * H + kk + acol4);
        As[acol4 + 0][arow] = av.x;
        As[acol4 + 1][arow] = av.y;
        As[acol4 + 2][arow] = av.z;
        As[acol4 + 3][arow] = av.w;

        if (tid < 128) {
            float4 wv = *(const float4*)(W + (size_t)(kk + wrow) * C + wcol4);
            *(float4*)&Bs[wrow][wcol4] = wv;
        }
        __syncthreads();

#pragma unroll
        for (int k = 0; k < 8; k++) {
            float4 a0 = *(const float4*)&As[k][ty * 8];
            float4 a1 = *(const float4*)&As[k][ty * 8 + 4];
            float4 bv = *(const float4*)&Bs[k][tx * 4];
            float a[8] = {a0.x, a0.y, a0.z, a0.w, a1.x, a1.y, a1.z, a1.w};
            float bb[4] = {bv.x, bv.y, bv.z, bv.w};
#pragma unroll
            for (int i = 0; i < 8; i++)
#pragma unroll
                for (int j = 0; j < 4; j++) acc[i][j] += a[i] * bb[j];
        }
        __syncthreads();
    }

#pragma unroll
    for (int i = 0; i < 8; i++) {
        int gr = block_row + ty * 8 + i;
        if (gr < n) {
            int cc = tx * 4;
            float4 v;
            v.x = acc[i][0] + b[cc + 0];
            v.y = acc[i][1] + b[cc + 1];
            v.z = acc[i][2] + b[cc + 2];
            v.w = acc[i][3] + b[cc + 3];
            *(float4*)(out + (size_t)gr * C + cc) = v;
        }
    }
}

// ---------------------------------------------------------------------------
// In-place row-wise log_softmax over C=64. One warp per row (2 cols / lane).
// ---------------------------------------------------------------------------
__global__ void __launch_bounds__(128) lsm_kernel(float* __restrict__ out, int n) {
    int r = blockIdx.x * 4 + (threadIdx.x >> 5);
    if (r >= n) return;
    int lane = threadIdx.x & 31;
    float* row = out + (size_t)r * C;
    float a = row[lane];
    float b = row[lane + 32];
    float m = fmaxf(a, b);
#pragma unroll
    for (int o = 16; o > 0; o >>= 1) m = fmaxf(m, __shfl_xor_sync(0xffffffffu, m, o));
    float s = expf(a - m) + expf(b - m);
#pragma unroll
    for (int o = 16; o > 0; o >>= 1) s += __shfl_xor_sync(0xffffffffu, s, o);
    float lg = m + logf(s);
    row[lane]      = a - lg;
    row[lane + 32] = b - lg;
}

// ---------------------------------------------------------------------------
extern "C" void kernel_launch(void* const* d_in, const int* in_sizes, int n_in,
                              void* d_out, int out_size) {
    const float* x      = (const float*)d_in[0];
    const int*   ei     = (const int*)  d_in[1];
    // d_in[2] = edge_attr (ignored by GIN)
    const float* conv_w = (const float*)d_in[3];
    const float* conv_b = (const float*)d_in[4];
    const float* bn_g   = (const float*)d_in[5];
    const float* bn_b   = (const float*)d_in[6];
    const float* bn_m   = (const float*)d_in[7];
    const float* bn_v   = (const float*)d_in[8];
    const float* fc_w   = (const float*)d_in[9];
    const float* fc_b   = (const float*)d_in[10];

    const int n  = in_sizes[0] / H;
    const int nE = in_sizes[1] / 2;
    const int* src = ei;
    const int* dst = ei + nE;

    float *hA, *hB, *sc, *bi;
    cudaGetSymbolAddress((void**)&hA, g_hA);
    cudaGetSymbolAddress((void**)&hB, g_hB);
    cudaGetSymbolAddress((void**)&sc, g_scale);
    cudaGetSymbolAddress((void**)&bi, g_bias);

    setup_kernel<<<3, 256>>>(conv_b, bn_g, bn_b, bn_m, bn_v);

    const size_t bytes = (size_t)n * H * sizeof(float);
    const int sblocks = (nE * 8 + 255) / 256;
    const int mblocks = (n + 127) / 128;

    // ---- GIN conv 1 ----
    cudaMemcpyAsync(hB, x, bytes, cudaMemcpyDeviceToDevice);
    scatter_kernel<<<sblocks, 256>>>(x, src, dst, hB, nE);
    mlp_kernel<<<mblocks, 256>>>(hB, conv_w + 0 * H * H, sc + 0 * H, bi + 0 * H, hA, n);
    mlp_kernel<<<mblocks, 256>>>(hA, conv_w + 1 * H * H, sc + 1 * H, bi + 1 * H, hB, n);
    mlp_kernel<<<mblocks, 256>>>(hB, conv_w + 2 * H * H, sc + 2 * H, bi + 2 * H, hA, n);

    // ---- GIN conv 2 ----
    cudaMemcpyAsync(hB, hA, bytes, cudaMemcpyDeviceToDevice);
    scatter_kernel<<<sblocks, 256>>>(hA, src, dst, hB, nE);
    mlp_kernel<<<mblocks, 256>>>(hB, conv_w + 3 * H * H, sc + 3 * H, bi + 3 * H, hA, n);
    mlp_kernel<<<mblocks, 256>>>(hA, conv_w + 4 * H * H, sc + 4 * H, bi + 4 * H, hB, n);
    mlp_kernel<<<mblocks, 256>>>(hB, conv_w + 5 * H * H, sc + 5 * H, bi + 5 * H, hA, n);

    // ---- FC + log_softmax ----
    fc_kernel<<<mblocks, 256>>>(hA, fc_w, fc_b, (float*)d_out, n);
    lsm_kernel<<<(n + 3) / 4, 128>>>((float*)d_out, n);
}

// round 3
// speedup vs baseline: 1.5370x; 1.5370x over previous
#include <cuda_runtime.h>
#include <math.h>
#include <stdint.h>

#define H 128
#define C 64
#define MAXN 100000

// Scratch (allocation-free rule: __device__ globals)
__device__ float g_hA[(size_t)MAXN * H];
__device__ float g_hB[(size_t)MAXN * H];
__device__ float g_scale[6 * H];
__device__ float g_bias[6 * H];

// ---------------------------------------------------------------------------
// Fold BN into per-column scale/bias
// ---------------------------------------------------------------------------
__global__ void setup_kernel(const float* __restrict__ conv_b,
                             const float* __restrict__ bn_g,
                             const float* __restrict__ bn_b,
                             const float* __restrict__ bn_m,
                             const float* __restrict__ bn_v) {
    int i = blockIdx.x * blockDim.x + threadIdx.x;
    if (i >= 6 * H) return;
    float s = bn_g[i] * rsqrtf(bn_v[i] + 1e-5f);
    g_scale[i] = s;
    g_bias[i]  = (conv_b[i] - bn_m[i]) * s + bn_b[i];
}

// ---------------------------------------------------------------------------
// Edge scatter-add: buf[dst] += h[src], 8 threads/edge, float4 vector REDs
// ---------------------------------------------------------------------------
__device__ __forceinline__ void red_add_v4(float* p, float4 v) {
    asm volatile("red.global.add.v4.f32 [%0], {%1, %2, %3, %4};"
                 :: "l"(p), "f"(v.x), "f"(v.y), "f"(v.z), "f"(v.w)
                 : "memory");
}

__global__ void __launch_bounds__(256) scatter_kernel(
        const float* __restrict__ h, const int* __restrict__ src,
        const int* __restrict__ dst, float* __restrict__ buf, int nE) {
    int i = blockIdx.x * blockDim.x + threadIdx.x;
    if (i >= nE * 8) return;
    int e = i >> 3;
    int c = (i & 7) << 4;               // 16-float chunk per thread
    int s = src[e], d = dst[e];
    const float4* hp = (const float4*)(h + (size_t)s * H + c);
    float* bp = buf + (size_t)d * H + c;
#pragma unroll
    for (int q = 0; q < 4; q++) {
        float4 v = hp[q];
        red_add_v4(bp + q * 4, v);
    }
}

// ---------------------------------------------------------------------------
// tf32 tensor-core MLP layer: out = relu((A @ W) * scale + bias)
// Block: 128x128 tile, K=128 in BK=32 chunks. 8 warps in 2x4 grid,
// warp tile 64x32 = 4x4 m16n8k8 mma tiles. Accum fp32.
// ---------------------------------------------------------------------------
__device__ __forceinline__ uint32_t f2tf(float f) {
    uint32_t r;
    asm("cvt.rna.tf32.f32 %0, %1;" : "=r"(r) : "f"(f));
    return r;
}

__device__ __forceinline__ void mma_tf32(float* d, const uint32_t* a, const uint32_t* b) {
    asm volatile(
        "mma.sync.aligned.m16n8k8.row.col.f32.tf32.tf32.f32 "
        "{%0,%1,%2,%3}, {%4,%5,%6,%7}, {%8,%9}, {%0,%1,%2,%3};"
        : "+f"(d[0]), "+f"(d[1]), "+f"(d[2]), "+f"(d[3])
        : "r"(a[0]), "r"(a[1]), "r"(a[2]), "r"(a[3]), "r"(b[0]), "r"(b[1]));
}

#define AP 36    // As pitch: bank = (4*m + k) % 32 -> frag-load conflict-free
#define BP 136   // Bs pitch: bank = (8*k + n) % 32 -> frag-load conflict-free

__global__ void __launch_bounds__(256) mlp_tc_kernel(
        const float* __restrict__ A, const float* __restrict__ W,
        const float* __restrict__ scale, const float* __restrict__ bias,
        float* __restrict__ out, int n) {
    __shared__ uint32_t As[128 * AP];   // [m][k] tf32 bits
    __shared__ uint32_t Bs[32 * BP];    // [k][n] tf32 bits

    const int tid  = threadIdx.x;
    const int lane = tid & 31;
    const int wid  = tid >> 5;
    const int gid  = lane >> 2;         // 0..7
    const int tig  = lane & 3;          // 0..3
    const int m0   = (wid & 1) * 64;
    const int n0   = (wid >> 1) * 32;
    const int block_row = blockIdx.x * 128;

    float acc[4][4][4];
#pragma unroll
    for (int i = 0; i < 4; i++)
#pragma unroll
        for (int j = 0; j < 4; j++)
#pragma unroll
            for (int r = 0; r < 4; r++) acc[i][j][r] = 0.f;

    const int arow = tid >> 3;          // 0..31
    const int ac4  = (tid & 7) * 4;     // A chunk col (0..28)

    for (int kk = 0; kk < H; kk += 32) {
        // A chunk: 128 rows x 32 k
#pragma unroll
        for (int r = 0; r < 4; r++) {
            int mrow = arow + r * 32;
            int gr = block_row + mrow;
            float4 v = make_float4(0.f, 0.f, 0.f, 0.f);
            if (gr < n) v = *(const float4*)(A + (size_t)gr * H + kk + ac4);
            uint32_t* p = &As[mrow * AP + ac4];
            p[0] = f2tf(v.x); p[1] = f2tf(v.y); p[2] = f2tf(v.z); p[3] = f2tf(v.w);
        }
        // B chunk: 32 k-rows x 128 n
        {
            int brow = tid >> 3;
#pragma unroll
            for (int q = 0; q < 4; q++) {
                int bc = (tid & 7) * 4 + q * 32;
                float4 v = *(const float4*)(W + (size_t)(kk + brow) * H + bc);
                uint32_t* p = &Bs[brow * BP + bc];
                p[0] = f2tf(v.x); p[1] = f2tf(v.y); p[2] = f2tf(v.z); p[3] = f2tf(v.w);
            }
        }
        __syncthreads();

#pragma unroll
        for (int ks = 0; ks < 4; ks++) {
            const int kq = ks * 8;
            uint32_t a[4][4], b[4][2];
#pragma unroll
            for (int i = 0; i < 4; i++) {
                int mr = m0 + i * 16 + gid;
                a[i][0] = As[mr * AP + kq + tig];
                a[i][1] = As[(mr + 8) * AP + kq + tig];
                a[i][2] = As[mr * AP + kq + tig + 4];
                a[i][3] = As[(mr + 8) * AP + kq + tig + 4];
            }
#pragma unroll
            for (int j = 0; j < 4; j++) {
                int nc = n0 + j * 8 + gid;
                b[j][0] = Bs[(kq + tig) * BP + nc];
                b[j][1] = Bs[(kq + tig + 4) * BP + nc];
            }
#pragma unroll
            for (int i = 0; i < 4; i++)
#pragma unroll
                for (int j = 0; j < 4; j++) mma_tf32(acc[i][j], a[i], b[j]);
        }
        __syncthreads();
    }

    // Epilogue: affine + relu, float2 stores. cols = n0 + j*8 + 2*tig (+1)
    float sc0[4], sc1[4], bi0[4], bi1[4];
#pragma unroll
    for (int j = 0; j < 4; j++) {
        int c = n0 + j * 8 + 2 * tig;
        sc0[j] = scale[c];     sc1[j] = scale[c + 1];
        bi0[j] = bias[c];      bi1[j] = bias[c + 1];
    }
#pragma unroll
    for (int i = 0; i < 4; i++) {
        int r0 = block_row + m0 + i * 16 + gid;
        int r1 = r0 + 8;
#pragma unroll
        for (int j = 0; j < 4; j++) {
            int c = n0 + j * 8 + 2 * tig;
            if (r0 < n) {
                float2 v;
                v.x = fmaxf(fmaf(acc[i][j][0], sc0[j], bi0[j]), 0.f);
                v.y = fmaxf(fmaf(acc[i][j][1], sc1[j], bi1[j]), 0.f);
                *(float2*)(out + (size_t)r0 * H + c) = v;
            }
            if (r1 < n) {
                float2 v;
                v.x = fmaxf(fmaf(acc[i][j][2], sc0[j], bi0[j]), 0.f);
                v.y = fmaxf(fmaf(acc[i][j][3], sc1[j], bi1[j]), 0.f);
                *(float2*)(out + (size_t)r1 * H + c) = v;
            }
        }
    }
}

// ---------------------------------------------------------------------------
// FC: [n,128] @ [128,64] + bias -> logits (fp32, minor cost)
// ---------------------------------------------------------------------------
__global__ void __launch_bounds__(256) fc_kernel(
        const float* __restrict__ A, const float* __restrict__ W,
        const float* __restrict__ b, float* __restrict__ out, int n) {
    __shared__ float As[8][132];
    __shared__ float Bs[8][68];

    const int tid = threadIdx.x;
    const int tx = tid & 15;
    const int ty = tid >> 4;
    const int block_row = blockIdx.x * 128;

    const int arow  = tid >> 1;
    const int acol4 = (tid & 1) * 4;
    const int wrow  = tid >> 4;
    const int wcol4 = (tid & 15) * 4;

    float acc[8][4];
#pragma unroll
    for (int i = 0; i < 8; i++)
#pragma unroll
        for (int j = 0; j < 4; j++) acc[i][j] = 0.f;

    for (int kk = 0; kk < H; kk += 8) {
        int gr = block_row + arow;
        float4 av = make_float4(0.f, 0.f, 0.f, 0.f);
        if (gr < n) av = *(const float4*)(A + (size_t)gr * H + kk + acol4);
        As[acol4 + 0][arow] = av.x;
        As[acol4 + 1][arow] = av.y;
        As[acol4 + 2][arow] = av.z;
        As[acol4 + 3][arow] = av.w;

        if (tid < 128) {
            float4 wv = *(const float4*)(W + (size_t)(kk + wrow) * C + wcol4);
            *(float4*)&Bs[wrow][wcol4] = wv;
        }
        __syncthreads();

#pragma unroll
        for (int k = 0; k < 8; k++) {
            float4 a0 = *(const float4*)&As[k][ty * 8];
            float4 a1 = *(const float4*)&As[k][ty * 8 + 4];
            float4 bv = *(const float4*)&Bs[k][tx * 4];
            float a[8] = {a0.x, a0.y, a0.z, a0.w, a1.x, a1.y, a1.z, a1.w};
            float bb[4] = {bv.x, bv.y, bv.z, bv.w};
#pragma unroll
            for (int i = 0; i < 8; i++)
#pragma unroll
                for (int j = 0; j < 4; j++) acc[i][j] += a[i] * bb[j];
        }
        __syncthreads();
    }

#pragma unroll
    for (int i = 0; i < 8; i++) {
        int gr = block_row + ty * 8 + i;
        if (gr < n) {
            int cc = tx * 4;
            float4 v;
            v.x = acc[i][0] + b[cc + 0];
            v.y = acc[i][1] + b[cc + 1];
            v.z = acc[i][2] + b[cc + 2];
            v.w = acc[i][3] + b[cc + 3];
            *(float4*)(out + (size_t)gr * C + cc) = v;
        }
    }
}

// ---------------------------------------------------------------------------
// In-place row-wise log_softmax over C=64. One warp per row.
// ---------------------------------------------------------------------------
__global__ void __launch_bounds__(128) lsm_kernel(float* __restrict__ out, int n) {
    int r = blockIdx.x * 4 + (threadIdx.x >> 5);
    if (r >= n) return;
    int lane = threadIdx.x & 31;
    float* row = out + (size_t)r * C;
    float a = row[lane];
    float b = row[lane + 32];
    float m = fmaxf(a, b);
#pragma unroll
    for (int o = 16; o > 0; o >>= 1) m = fmaxf(m, __shfl_xor_sync(0xffffffffu, m, o));
    float s = expf(a - m) + expf(b - m);
#pragma unroll
    for (int o = 16; o > 0; o >>= 1) s += __shfl_xor_sync(0xffffffffu, s, o);
    float lg = m + logf(s);
    row[lane]      = a - lg;
    row[lane + 32] = b - lg;
}

// ---------------------------------------------------------------------------
extern "C" void kernel_launch(void* const* d_in, const int* in_sizes, int n_in,
                              void* d_out, int out_size) {
    const float* x      = (const float*)d_in[0];
    const int*   ei     = (const int*)  d_in[1];
    // d_in[2] = edge_attr (ignored by GIN)
    const float* conv_w = (const float*)d_in[3];
    const float* conv_b = (const float*)d_in[4];
    const float* bn_g   = (const float*)d_in[5];
    const float* bn_b   = (const float*)d_in[6];
    const float* bn_m   = (const float*)d_in[7];
    const float* bn_v   = (const float*)d_in[8];
    const float* fc_w   = (const float*)d_in[9];
    const float* fc_b   = (const float*)d_in[10];

    const int n  = in_sizes[0] / H;
    const int nE = in_sizes[1] / 2;
    const int* src = ei;
    const int* dst = ei + nE;

    float *hA, *hB, *sc, *bi;
    cudaGetSymbolAddress((void**)&hA, g_hA);
    cudaGetSymbolAddress((void**)&hB, g_hB);
    cudaGetSymbolAddress((void**)&sc, g_scale);
    cudaGetSymbolAddress((void**)&bi, g_bias);

    setup_kernel<<<3, 256>>>(conv_b, bn_g, bn_b, bn_m, bn_v);

    const size_t bytes = (size_t)n * H * sizeof(float);
    const int sblocks = (nE * 8 + 255) / 256;
    const int mblocks = (n + 127) / 128;

    // ---- GIN conv 1 ----
    cudaMemcpyAsync(hB, x, bytes, cudaMemcpyDeviceToDevice);
    scatter_kernel<<<sblocks, 256>>>(x, src, dst, hB, nE);
    mlp_tc_kernel<<<mblocks, 256>>>(hB, conv_w + 0 * H * H, sc + 0 * H, bi + 0 * H, hA, n);
    mlp_tc_kernel<<<mblocks, 256>>>(hA, conv_w + 1 * H * H, sc + 1 * H, bi + 1 * H, hB, n);
    mlp_tc_kernel<<<mblocks, 256>>>(hB, conv_w + 2 * H * H, sc + 2 * H, bi + 2 * H, hA, n);

    // ---- GIN conv 2 ----
    cudaMemcpyAsync(hB, hA, bytes, cudaMemcpyDeviceToDevice);
    scatter_kernel<<<sblocks, 256>>>(hA, src, dst, hB, nE);
    mlp_tc_kernel<<<mblocks, 256>>>(hB, conv_w + 3 * H * H, sc + 3 * H, bi + 3 * H, hA, n);
    mlp_tc_kernel<<<mblocks, 256>>>(hA, conv_w + 4 * H * H, sc + 4 * H, bi + 4 * H, hB, n);
    mlp_tc_kernel<<<mblocks, 256>>>(hB, conv_w + 5 * H * H, sc + 5 * H, bi + 5 * H, hA, n);

    // ---- FC + log_softmax ----
    fc_kernel<<<mblocks, 256>>>(hA, fc_w, fc_b, (float*)d_out, n);
    lsm_kernel<<<(n + 3) / 4, 128>>>((float*)d_out, n);
}

// round 7
// speedup vs baseline: 2.7273x; 1.7745x over previous
#include <cuda_runtime.h>
#include <math.h>
#include <stdint.h>

#define H 128
#define C 64
#define MAXN 100000
#define MAXE 1600000

// Scratch (allocation-free rule: __device__ globals)
__device__ float g_hA[(size_t)MAXN * H];
__device__ float g_hB[(size_t)MAXN * H];
__device__ float g_scale[6 * H];
__device__ float g_bias[6 * H];
__device__ int   g_deg[MAXN];
__device__ int   g_off[MAXN];
__device__ int   g_cur[MAXN];
__device__ int   g_csr[MAXE];
__device__ int   g_part[128];

// ---------------------------------------------------------------------------
// Fold BN into per-column scale/bias
// ---------------------------------------------------------------------------
__global__ void setup_kernel(const float* __restrict__ conv_b,
                             const float* __restrict__ bn_g,
                             const float* __restrict__ bn_b,
                             const float* __restrict__ bn_m,
                             const float* __restrict__ bn_v) {
    int i = blockIdx.x * blockDim.x + threadIdx.x;
    if (i >= 6 * H) return;
    float s = bn_g[i] * rsqrtf(bn_v[i] + 1e-5f);
    g_scale[i] = s;
    g_bias[i]  = (conv_b[i] - bn_m[i]) * s + bn_b[i];
}

// ---------------------------------------------------------------------------
// CSR build: histogram -> exclusive scan -> fill
// ---------------------------------------------------------------------------
__global__ void zero_kernel(int nN) {
    int i = blockIdx.x * blockDim.x + threadIdx.x;
    if (i < nN) { g_deg[i] = 0; g_cur[i] = 0; }
}

__global__ void hist_kernel(const int* __restrict__ dst, int nE) {
    int e = blockIdx.x * blockDim.x + threadIdx.x;
    if (e < nE) atomicAdd(&g_deg[dst[e]], 1);
}

__global__ void __launch_bounds__(1024) scanA_kernel(int nN) {
    __shared__ int s[1024];
    int tid = threadIdx.x;
    int idx = blockIdx.x * 1024 + tid;
    int v = (idx < nN) ? g_deg[idx] : 0;
    s[tid] = v;
    __syncthreads();
#pragma unroll
    for (int o = 1; o < 1024; o <<= 1) {
        int t = (tid >= o) ? s[tid - o] : 0;
        __syncthreads();
        s[tid] += t;
        __syncthreads();
    }
    int incl = s[tid];
    if (idx < nN) g_off[idx] = incl - v;
    if (tid == 1023) g_part[blockIdx.x] = incl;
}

__global__ void scanB_kernel(int nb) {
    if (threadIdx.x == 0) {
        int run = 0;
        for (int i = 0; i < nb && i < 128; i++) {
            int t = g_part[i]; g_part[i] = run; run += t;
        }
    }
}

__global__ void __launch_bounds__(1024) scanC_kernel(int nN) {
    int idx = blockIdx.x * 1024 + threadIdx.x;
    if (idx < nN && blockIdx.x > 0) g_off[idx] += g_part[blockIdx.x];
}

__global__ void fill_kernel(const int* __restrict__ src,
                            const int* __restrict__ dst, int nE) {
    int e = blockIdx.x * blockDim.x + threadIdx.x;
    if (e >= nE) return;
    int d = dst[e];
    int pos = g_off[d] + atomicAdd(&g_cur[d], 1);
    g_csr[pos] = src[e];
}

// ---------------------------------------------------------------------------
// Gather-reduce: out[i] = h[i] + sum_{j in in(i)} h[j].  One warp per node,
// lane owns one float4 column chunk. No atomics, single coalesced write.
// ---------------------------------------------------------------------------
__global__ void __launch_bounds__(256) gather_kernel(
        const float* __restrict__ h, float* __restrict__ out, int nN) {
    int w = (blockIdx.x * 256 + threadIdx.x) >> 5;
    if (w >= nN) return;
    int lane = threadIdx.x & 31;
    const float4* hp = (const float4*)h;

    float4 acc = hp[(size_t)w * 32 + lane];     // self term (replaces memcpy)
    int start = g_off[w];
    int deg   = g_deg[w];

    for (int base = 0; base < deg; base += 32) {
        int cnt = deg - base;
        if (cnt > 32) cnt = 32;
        int e = (lane < cnt) ? g_csr[start + base + lane] : 0;
        int j = 0;
        // process 4 edges/iteration for load-level parallelism
        for (; j + 4 <= cnt; j += 4) {
            int s0 = __shfl_sync(0xffffffffu, e, j);
            int s1 = __shfl_sync(0xffffffffu, e, j + 1);
            int s2 = __shfl_sync(0xffffffffu, e, j + 2);
            int s3 = __shfl_sync(0xffffffffu, e, j + 3);
            float4 v0 = hp[(size_t)s0 * 32 + lane];
            float4 v1 = hp[(size_t)s1 * 32 + lane];
            float4 v2 = hp[(size_t)s2 * 32 + lane];
            float4 v3 = hp[(size_t)s3 * 32 + lane];
            acc.x += v0.x + v1.x + v2.x + v3.x;
            acc.y += v0.y + v1.y + v2.y + v3.y;
            acc.z += v0.z + v1.z + v2.z + v3.z;
            acc.w += v0.w + v1.w + v2.w + v3.w;
        }
        for (; j < cnt; j++) {
            int s = __shfl_sync(0xffffffffu, e, j);
            float4 v = hp[(size_t)s * 32 + lane];
            acc.x += v.x; acc.y += v.y; acc.z += v.z; acc.w += v.w;
        }
    }
    ((float4*)out)[(size_t)w * 32 + lane] = acc;
}

// ---------------------------------------------------------------------------
// tf32 tensor-core MLP layer: out = relu((A @ W) * scale + bias)
// ---------------------------------------------------------------------------
__device__ __forceinline__ uint32_t f2tf(float f) {
    uint32_t r;
    asm("cvt.rna.tf32.f32 %0, %1;" : "=r"(r) : "f"(f));
    return r;
}

__device__ __forceinline__ void mma_tf32(float* d, const uint32_t* a, const uint32_t* b) {
    asm volatile(
        "mma.sync.aligned.m16n8k8.row.col.f32.tf32.tf32.f32 "
        "{%0,%1,%2,%3}, {%4,%5,%6,%7}, {%8,%9}, {%0,%1,%2,%3};"
        : "+f"(d[0]), "+f"(d[1]), "+f"(d[2]), "+f"(d[3])
        : "r"(a[0]), "r"(a[1]), "r"(a[2]), "r"(a[3]), "r"(b[0]), "r"(b[1]));
}

#define AP 36    // As pitch: conflict-free fragment loads
#define BP 136   // Bs pitch: conflict-free fragment loads

__global__ void __launch_bounds__(256) mlp_tc_kernel(
        const float* __restrict__ A, const float* __restrict__ W,
        const float* __restrict__ scale, const float* __restrict__ bias,
        float* __restrict__ out, int n) {
    __shared__ uint32_t As[128 * AP];   // [m][k] tf32 bits
    __shared__ uint32_t Bs[32 * BP];    // [k][n] tf32 bits

    const int tid  = threadIdx.x;
    const int lane = tid & 31;
    const int wid  = tid >> 5;
    const int gid  = lane >> 2;
    const int tig  = lane & 3;
    const int m0   = (wid & 1) * 64;
    const int n0   = (wid >> 1) * 32;
    const int block_row = blockIdx.x * 128;

    float acc[4][4][4];
#pragma unroll
    for (int i = 0; i < 4; i++)
#pragma unroll
        for (int j = 0; j < 4; j++)
#pragma unroll
            for (int r = 0; r < 4; r++) acc[i][j][r] = 0.f;

    const int arow = tid >> 3;
    const int ac4  = (tid & 7) * 4;

    for (int kk = 0; kk < H; kk += 32) {
#pragma unroll
        for (int r = 0; r < 4; r++) {
            int mrow = arow + r * 32;
            int gr = block_row + mrow;
            float4 v = make_float4(0.f, 0.f, 0.f, 0.f);
            if (gr < n) v = *(const float4*)(A + (size_t)gr * H + kk + ac4);
            uint32_t* p = &As[mrow * AP + ac4];
            p[0] = f2tf(v.x); p[1] = f2tf(v.y); p[2] = f2tf(v.z); p[3] = f2tf(v.w);
        }
        {
            int brow = tid >> 3;
#pragma unroll
            for (int q = 0; q < 4; q++) {
                int bc = (tid & 7) * 4 + q * 32;
                float4 v = *(const float4*)(W + (size_t)(kk + brow) * H + bc);
                uint32_t* p = &Bs[brow * BP + bc];
                p[0] = f2tf(v.x); p[1] = f2tf(v.y); p[2] = f2tf(v.z); p[3] = f2tf(v.w);
            }
        }
        __syncthreads();

#pragma unroll
        for (int ks = 0; ks < 4; ks++) {
            const int kq = ks * 8;
            uint32_t a[4][4], b[4][2];
#pragma unroll
            for (int i = 0; i < 4; i++) {
                int mr = m0 + i * 16 + gid;
                a[i][0] = As[mr * AP + kq + tig];
                a[i][1] = As[(mr + 8) * AP + kq + tig];
                a[i][2] = As[mr * AP + kq + tig + 4];
                a[i][3] = As[(mr + 8) * AP + kq + tig + 4];
            }
#pragma unroll
            for (int j = 0; j < 4; j++) {
                int nc = n0 + j * 8 + gid;
                b[j][0] = Bs[(kq + tig) * BP + nc];
                b[j][1] = Bs[(kq + tig + 4) * BP + nc];
            }
#pragma unroll
            for (int i = 0; i < 4; i++)
#pragma unroll
                for (int j = 0; j < 4; j++) mma_tf32(acc[i][j], a[i], b[j]);
        }
        __syncthreads();
    }

    float sc0[4], sc1[4], bi0[4], bi1[4];
#pragma unroll
    for (int j = 0; j < 4; j++) {
        int c = n0 + j * 8 + 2 * tig;
        sc0[j] = scale[c];     sc1[j] = scale[c + 1];
        bi0[j] = bias[c];      bi1[j] = bias[c + 1];
    }
#pragma unroll
    for (int i = 0; i < 4; i++) {
        int r0 = block_row + m0 + i * 16 + gid;
        int r1 = r0 + 8;
#pragma unroll
        for (int j = 0; j < 4; j++) {
            int c = n0 + j * 8 + 2 * tig;
            if (r0 < n) {
                float2 v;
                v.x = fmaxf(fmaf(acc[i][j][0], sc0[j], bi0[j]), 0.f);
                v.y = fmaxf(fmaf(acc[i][j][1], sc1[j], bi1[j]), 0.f);
                *(float2*)(out + (size_t)r0 * H + c) = v;
            }
            if (r1 < n) {
                float2 v;
                v.x = fmaxf(fmaf(acc[i][j][2], sc0[j], bi0[j]), 0.f);
                v.y = fmaxf(fmaf(acc[i][j][3], sc1[j], bi1[j]), 0.f);
                *(float2*)(out + (size_t)r1 * H + c) = v;
            }
        }
    }
}

// ---------------------------------------------------------------------------
// FC: [n,128] @ [128,64] + bias -> logits
// ---------------------------------------------------------------------------
__global__ void __launch_bounds__(256) fc_kernel(
        const float* __restrict__ A, const float* __restrict__ W,
        const float* __restrict__ b, float* __restrict__ out, int n) {
    __shared__ float As[8][132];
    __shared__ float Bs[8][68];

    const int tid = threadIdx.x;
    const int tx = tid & 15;
    const int ty = tid >> 4;
    const int block_row = blockIdx.x * 128;

    const int arow  = tid >> 1;
    const int acol4 = (tid & 1) * 4;
    const int wrow  = tid >> 4;
    const int wcol4 = (tid & 15) * 4;

    float acc[8][4];
#pragma unroll
    for (int i = 0; i < 8; i++)
#pragma unroll
        for (int j = 0; j < 4; j++) acc[i][j] = 0.f;

    for (int kk = 0; kk < H; kk += 8) {
        int gr = block_row + arow;
        float4 av = make_float4(0.f, 0.f, 0.f, 0.f);
        if (gr < n) av = *(const float4*)(A + (size_t)gr * H + kk + acol4);
        As[acol4 + 0][arow] = av.x;
        As[acol4 + 1][arow] = av.y;
        As[acol4 + 2][arow] = av.z;
        As[acol4 + 3][arow] = av.w;

        if (tid < 128) {
            float4 wv = *(const float4*)(W + (size_t)(kk + wrow) * C + wcol4);
            *(float4*)&Bs[wrow][wcol4] = wv;
        }
        __syncthreads();

#pragma unroll
        for (int k = 0; k < 8; k++) {
            float4 a0 = *(const float4*)&As[k][ty * 8];
            float4 a1 = *(const float4*)&As[k][ty * 8 + 4];
            float4 bv = *(const float4*)&Bs[k][tx * 4];
            float a[8] = {a0.x, a0.y, a0.z, a0.w, a1.x, a1.y, a1.z, a1.w};
            float bb[4] = {bv.x, bv.y, bv.z, bv.w};
#pragma unroll
            for (int i = 0; i < 8; i++)
#pragma unroll
                for (int j = 0; j < 4; j++) acc[i][j] += a[i] * bb[j];
        }
        __syncthreads();
    }

#pragma unroll
    for (int i = 0; i < 8; i++) {
        int gr = block_row + ty * 8 + i;
        if (gr < n) {
            int cc = tx * 4;
            float4 v;
            v.x = acc[i][0] + b[cc + 0];
            v.y = acc[i][1] + b[cc + 1];
            v.z = acc[i][2] + b[cc + 2];
            v.w = acc[i][3] + b[cc + 3];
            *(float4*)(out + (size_t)gr * C + cc) = v;
        }
    }
}

// ---------------------------------------------------------------------------
// In-place row-wise log_softmax over C=64. One warp per row.
// ---------------------------------------------------------------------------
__global__ void __launch_bounds__(128) lsm_kernel(float* __restrict__ out, int n) {
    int r = blockIdx.x * 4 + (threadIdx.x >> 5);
    if (r >= n) return;
    int lane = threadIdx.x & 31;
    float* row = out + (size_t)r * C;
    float a = row[lane];
    float b = row[lane + 32];
    float m = fmaxf(a, b);
#pragma unroll
    for (int o = 16; o > 0; o >>= 1) m = fmaxf(m, __shfl_xor_sync(0xffffffffu, m, o));
    float s = expf(a - m) + expf(b - m);
#pragma unroll
    for (int o = 16; o > 0; o >>= 1) s += __shfl_xor_sync(0xffffffffu, s, o);
    float lg = m + logf(s);
    row[lane]      = a - lg;
    row[lane + 32] = b - lg;
}

// ---------------------------------------------------------------------------
extern "C" void kernel_launch(void* const* d_in, const int* in_sizes, int n_in,
                              void* d_out, int out_size) {
    const float* x      = (const float*)d_in[0];
    const int*   ei     = (const int*)  d_in[1];
    // d_in[2] = edge_attr (ignored by GIN)
    const float* conv_w = (const float*)d_in[3];
    const float* conv_b = (const float*)d_in[4];
    const float* bn_g   = (const float*)d_in[5];
    const float* bn_b   = (const float*)d_in[6];
    const float* bn_m   = (const float*)d_in[7];
    const float* bn_v   = (const float*)d_in[8];
    const float* fc_w   = (const float*)d_in[9];
    const float* fc_b   = (const float*)d_in[10];

    const int n  = in_sizes[0] / H;
    const int nE = in_sizes[1] / 2;
    const int* src = ei;
    const int* dst = ei + nE;

    float *hA, *hB, *sc, *bi;
    cudaGetSymbolAddress((void**)&hA, g_hA);
    cudaGetSymbolAddress((void**)&hB, g_hB);
    cudaGetSymbolAddress((void**)&sc, g_scale);
    cudaGetSymbolAddress((void**)&bi, g_bias);

    setup_kernel<<<3, 256>>>(conv_b, bn_g, bn_b, bn_m, bn_v);

    // ---- CSR build (once per launch; reused by both convs) ----
    const int nb = (n + 1023) / 1024;
    zero_kernel<<<(n + 255) / 256, 256>>>(n);
    hist_kernel<<<(nE + 255) / 256, 256>>>(dst, nE);
    scanA_kernel<<<nb, 1024>>>(n);
    scanB_kernel<<<1, 32>>>(nb);
    scanC_kernel<<<nb, 1024>>>(n);
    fill_kernel<<<(nE + 255) / 256, 256>>>(src, dst, nE);

    const int gblocks = (n * 32 + 255) / 256;   // one warp per node
    const int mblocks = (n + 127) / 128;

    // ---- GIN conv 1 ----
    gather_kernel<<<gblocks, 256>>>(x, hB, n);
    mlp_tc_kernel<<<mblocks, 256>>>(hB, conv_w + 0 * H * H, sc + 0 * H, bi + 0 * H, hA, n);
    mlp_tc_kernel<<<mblocks, 256>>>(hA, conv_w + 1 * H * H, sc + 1 * H, bi + 1 * H, hB, n);
    mlp_tc_kernel<<<mblocks, 256>>>(hB, conv_w + 2 * H * H, sc + 2 * H, bi + 2 * H, hA, n);

    // ---- GIN conv 2 ----
    gather_kernel<<<gblocks, 256>>>(hA, hB, n);
    mlp_tc_kernel<<<mblocks, 256>>>(hB, conv_w + 3 * H * H, sc + 3 * H, bi + 3 * H, hA, n);
    mlp_tc_kernel<<<mblocks, 256>>>(hA, conv_w + 4 * H * H, sc + 4 * H, bi + 4 * H, hB, n);
    mlp_tc_kernel<<<mblocks, 256>>>(hB, conv_w + 5 * H * H, sc + 5 * H, bi + 5 * H, hA, n);

    // ---- FC + log_softmax ----
    fc_kernel<<<mblocks, 256>>>(hA, fc_w, fc_b, (float*)d_out, n);
    lsm_kernel<<<(n + 3) / 4, 128>>>((float*)d_out, n);
}

// round 8
// speedup vs baseline: 2.9870x; 1.0952x over previous
#include <cuda_runtime.h>
#include <math.h>
#include <stdint.h>

#define H 128
#define C 64
#define MAXN 100000
#define MAXE 1600000

// Scratch (allocation-free rule: __device__ globals)
__device__ float g_hA[(size_t)MAXN * H];
__device__ float g_hB[(size_t)MAXN * H];
__device__ float g_scale[6 * H];
__device__ float g_bias[6 * H];
__device__ int   g_deg[MAXN];
__device__ int   g_off[MAXN];
__device__ int   g_cur[MAXN];
__device__ int   g_csr[MAXE];
__device__ int   g_part[128];

// ---------------------------------------------------------------------------
// Fold BN into per-column scale/bias
// ---------------------------------------------------------------------------
__global__ void setup_kernel(const float* __restrict__ conv_b,
                             const float* __restrict__ bn_g,
                             const float* __restrict__ bn_b,
                             const float* __restrict__ bn_m,
                             const float* __restrict__ bn_v) {
    int i = blockIdx.x * blockDim.x + threadIdx.x;
    if (i >= 6 * H) return;
    float s = bn_g[i] * rsqrtf(bn_v[i] + 1e-5f);
    g_scale[i] = s;
    g_bias[i]  = (conv_b[i] - bn_m[i]) * s + bn_b[i];
}

// ---------------------------------------------------------------------------
// CSR build: histogram -> exclusive scan -> fill
// ---------------------------------------------------------------------------
__global__ void zero_kernel(int nN) {
    int i = blockIdx.x * blockDim.x + threadIdx.x;
    if (i < nN) { g_deg[i] = 0; g_cur[i] = 0; }
}

__global__ void hist_kernel(const int* __restrict__ dst, int nE) {
    int e = blockIdx.x * blockDim.x + threadIdx.x;
    if (e < nE) atomicAdd(&g_deg[dst[e]], 1);
}

__global__ void __launch_bounds__(1024) scanA_kernel(int nN) {
    __shared__ int s[1024];
    int tid = threadIdx.x;
    int idx = blockIdx.x * 1024 + tid;
    int v = (idx < nN) ? g_deg[idx] : 0;
    s[tid] = v;
    __syncthreads();
#pragma unroll
    for (int o = 1; o < 1024; o <<= 1) {
        int t = (tid >= o) ? s[tid - o] : 0;
        __syncthreads();
        s[tid] += t;
        __syncthreads();
    }
    int incl = s[tid];
    if (idx < nN) g_off[idx] = incl - v;
    if (tid == 1023) g_part[blockIdx.x] = incl;
}

__global__ void scanB_kernel(int nb) {
    if (threadIdx.x == 0) {
        int run = 0;
        for (int i = 0; i < nb && i < 128; i++) {
            int t = g_part[i]; g_part[i] = run; run += t;
        }
    }
}

__global__ void __launch_bounds__(1024) scanC_kernel(int nN) {
    int idx = blockIdx.x * 1024 + threadIdx.x;
    if (idx < nN && blockIdx.x > 0) g_off[idx] += g_part[blockIdx.x];
}

__global__ void fill_kernel(const int* __restrict__ src,
                            const int* __restrict__ dst, int nE) {
    int e = blockIdx.x * blockDim.x + threadIdx.x;
    if (e >= nE) return;
    int d = dst[e];
    int pos = g_off[d] + atomicAdd(&g_cur[d], 1);
    g_csr[pos] = src[e];
}

// ---------------------------------------------------------------------------
// Gather-reduce: out[i] = h[i] + sum_{j in in(i)} h[j].  One warp per node.
// ---------------------------------------------------------------------------
__global__ void __launch_bounds__(256) gather_kernel(
        const float* __restrict__ h, float* __restrict__ out, int nN) {
    int w = (blockIdx.x * 256 + threadIdx.x) >> 5;
    if (w >= nN) return;
    int lane = threadIdx.x & 31;
    const float4* hp = (const float4*)h;

    float4 acc = hp[(size_t)w * 32 + lane];     // self term
    int start = g_off[w];
    int deg   = g_deg[w];

    for (int base = 0; base < deg; base += 32) {
        int cnt = deg - base;
        if (cnt > 32) cnt = 32;
        int e = (lane < cnt) ? g_csr[start + base + lane] : 0;
        int j = 0;
        for (; j + 4 <= cnt; j += 4) {
            int s0 = __shfl_sync(0xffffffffu, e, j);
            int s1 = __shfl_sync(0xffffffffu, e, j + 1);
            int s2 = __shfl_sync(0xffffffffu, e, j + 2);
            int s3 = __shfl_sync(0xffffffffu, e, j + 3);
            float4 v0 = hp[(size_t)s0 * 32 + lane];
            float4 v1 = hp[(size_t)s1 * 32 + lane];
            float4 v2 = hp[(size_t)s2 * 32 + lane];
            float4 v3 = hp[(size_t)s3 * 32 + lane];
            acc.x += v0.x + v1.x + v2.x + v3.x;
            acc.y += v0.y + v1.y + v2.y + v3.y;
            acc.z += v0.z + v1.z + v2.z + v3.z;
            acc.w += v0.w + v1.w + v2.w + v3.w;
        }
        for (; j < cnt; j++) {
            int s = __shfl_sync(0xffffffffu, e, j);
            float4 v = hp[(size_t)s * 32 + lane];
            acc.x += v.x; acc.y += v.y; acc.z += v.z; acc.w += v.w;
        }
    }
    ((float4*)out)[(size_t)w * 32 + lane] = acc;
}

// ---------------------------------------------------------------------------
// Fused 3-layer tf32 MLP: out = L3(L2(L1(A))), Li = relu(affine(x @ Wi)).
// Block = 128 rows. H (the running activation) lives entirely in smem;
// each stage drains Hs into accumulators before the epilogue overwrites it.
// ---------------------------------------------------------------------------
__device__ __forceinline__ uint32_t f2tf(float f) {
    uint32_t r;
    asm("cvt.rna.tf32.f32 %0, %1;" : "=r"(r) : "f"(f));
    return r;
}

__device__ __forceinline__ void mma_tf32(float* d, const uint32_t* a, const uint32_t* b) {
    asm volatile(
        "mma.sync.aligned.m16n8k8.row.col.f32.tf32.tf32.f32 "
        "{%0,%1,%2,%3}, {%4,%5,%6,%7}, {%8,%9}, {%0,%1,%2,%3};"
        : "+f"(d[0]), "+f"(d[1]), "+f"(d[2]), "+f"(d[3])
        : "r"(a[0]), "r"(a[1]), "r"(a[2]), "r"(a[3]), "r"(b[0]), "r"(b[1]));
}

#define HP 132   // Hs pitch: bank = (4m+k)%32 -> conflict-free frag loads
#define BP 136   // Bs pitch: bank = (8k+n)%32 -> conflict-free frag loads
#define MLP3_SMEM ((128 * HP + 32 * BP) * 4)

__global__ void __launch_bounds__(256, 2) mlp3_tc_kernel(
        const float* __restrict__ A, const float* __restrict__ W,   // [3][H][H]
        const float* __restrict__ scale, const float* __restrict__ bias, // [3][H]
        float* __restrict__ out, int n) {
    extern __shared__ uint32_t sm[];
    uint32_t* Hs = sm;                  // 128 x HP tf32
    uint32_t* Bs = sm + 128 * HP;       // 32 x BP tf32

    const int tid  = threadIdx.x;
    const int lane = tid & 31;
    const int wid  = tid >> 5;
    const int gid  = lane >> 2;
    const int tig  = lane & 3;
    const int m0   = (wid & 1) * 64;
    const int n0   = (wid >> 1) * 32;
    const int block_row = blockIdx.x * 128;

    // Load A block -> Hs (tf32). Warp reads one full 512B row per iteration.
#pragma unroll
    for (int it = 0; it < 16; it++) {
        int idx = it * 256 + tid;       // 0..4095 float4s
        int row = idx >> 5;
        int c4  = (idx & 31) * 4;
        int gr  = block_row + row;
        float4 v = make_float4(0.f, 0.f, 0.f, 0.f);
        if (gr < n) v = *(const float4*)(A + (size_t)gr * H + c4);
        uint32_t* p = &Hs[row * HP + c4];
        p[0] = f2tf(v.x); p[1] = f2tf(v.y); p[2] = f2tf(v.z); p[3] = f2tf(v.w);
    }
    __syncthreads();

#pragma unroll 1
    for (int s = 0; s < 3; s++) {
        const float* Ws = W + s * H * H;

        float acc[4][4][4];
#pragma unroll
        for (int i = 0; i < 4; i++)
#pragma unroll
            for (int j = 0; j < 4; j++)
#pragma unroll
                for (int r = 0; r < 4; r++) acc[i][j][r] = 0.f;

        for (int kk = 0; kk < H; kk += 32) {
            // W chunk: 32 k-rows x 128 n
            {
                int brow = tid >> 3;
#pragma unroll
                for (int q = 0; q < 4; q++) {
                    int bc = (tid & 7) * 4 + q * 32;
                    float4 v = *(const float4*)(Ws + (size_t)(kk + brow) * H + bc);
                    uint32_t* p = &Bs[brow * BP + bc];
                    p[0] = f2tf(v.x); p[1] = f2tf(v.y); p[2] = f2tf(v.z); p[3] = f2tf(v.w);
                }
            }
            __syncthreads();

#pragma unroll
            for (int ks = 0; ks < 4; ks++) {
                const int kq = ks * 8;
                uint32_t a[4][4], b[4][2];
#pragma unroll
                for (int i = 0; i < 4; i++) {
                    int mr = m0 + i * 16 + gid;
                    a[i][0] = Hs[mr * HP + kk + kq + tig];
                    a[i][1] = Hs[(mr + 8) * HP + kk + kq + tig];
                    a[i][2] = Hs[mr * HP + kk + kq + tig + 4];
                    a[i][3] = Hs[(mr + 8) * HP + kk + kq + tig + 4];
                }
#pragma unroll
                for (int j = 0; j < 4; j++) {
                    int nc = n0 + j * 8 + gid;
                    b[j][0] = Bs[(kq + tig) * BP + nc];
                    b[j][1] = Bs[(kq + tig + 4) * BP + nc];
                }
#pragma unroll
                for (int i = 0; i < 4; i++)
#pragma unroll
                    for (int j = 0; j < 4; j++) mma_tf32(acc[i][j], a[i], b[j]);
            }
            __syncthreads();   // Bs reload + (last iter) Hs-drain barrier
        }

        // Epilogue: affine + relu
        const float* scp = scale + s * H;
        const float* bip = bias + s * H;
        float sc0[4], sc1[4], bi0[4], bi1[4];
#pragma unroll
        for (int j = 0; j < 4; j++) {
            int c = n0 + j * 8 + 2 * tig;
            sc0[j] = scp[c];     sc1[j] = scp[c + 1];
            bi0[j] = bip[c];     bi1[j] = bip[c + 1];
        }

        if (s < 2) {
            // write relu(affine) back into Hs as tf32 (next stage's A)
#pragma unroll
            for (int i = 0; i < 4; i++) {
                int r0 = m0 + i * 16 + gid;
                int r1 = r0 + 8;
#pragma unroll
                for (int j = 0; j < 4; j++) {
                    int c = n0 + j * 8 + 2 * tig;
                    Hs[r0 * HP + c]     = f2tf(fmaxf(fmaf(acc[i][j][0], sc0[j], bi0[j]), 0.f));
                    Hs[r0 * HP + c + 1] = f2tf(fmaxf(fmaf(acc[i][j][1], sc1[j], bi1[j]), 0.f));
                    Hs[r1 * HP + c]     = f2tf(fmaxf(fmaf(acc[i][j][2], sc0[j], bi0[j]), 0.f));
                    Hs[r1 * HP + c + 1] = f2tf(fmaxf(fmaf(acc[i][j][3], sc1[j], bi1[j]), 0.f));
                }
            }
            __syncthreads();
        } else {
            // final stage -> gmem fp32
#pragma unroll
            for (int i = 0; i < 4; i++) {
                int r0 = block_row + m0 + i * 16 + gid;
                int r1 = r0 + 8;
#pragma unroll
                for (int j = 0; j < 4; j++) {
                    int c = n0 + j * 8 + 2 * tig;
                    if (r0 < n) {
                        float2 v;
                        v.x = fmaxf(fmaf(acc[i][j][0], sc0[j], bi0[j]), 0.f);
                        v.y = fmaxf(fmaf(acc[i][j][1], sc1[j], bi1[j]), 0.f);
                        *(float2*)(out + (size_t)r0 * H + c) = v;
                    }
                    if (r1 < n) {
                        float2 v;
                        v.x = fmaxf(fmaf(acc[i][j][2], sc0[j], bi0[j]), 0.f);
                        v.y = fmaxf(fmaf(acc[i][j][3], sc1[j], bi1[j]), 0.f);
                        *(float2*)(out + (size_t)r1 * H + c) = v;
                    }
                }
            }
        }
    }
}

// ---------------------------------------------------------------------------
// FC: [n,128] @ [128,64] + bias -> logits
// ---------------------------------------------------------------------------
__global__ void __launch_bounds__(256) fc_kernel(
        const float* __restrict__ A, const float* __restrict__ W,
        const float* __restrict__ b, float* __restrict__ out, int n) {
    __shared__ float As[8][132];
    __shared__ float Bs[8][68];

    const int tid = threadIdx.x;
    const int tx = tid & 15;
    const int ty = tid >> 4;
    const int block_row = blockIdx.x * 128;

    const int arow  = tid >> 1;
    const int acol4 = (tid & 1) * 4;
    const int wrow  = tid >> 4;
    const int wcol4 = (tid & 15) * 4;

    float acc[8][4];
#pragma unroll
    for (int i = 0; i < 8; i++)
#pragma unroll
        for (int j = 0; j < 4; j++) acc[i][j] = 0.f;

    for (int kk = 0; kk < H; kk += 8) {
        int gr = block_row + arow;
        float4 av = make_float4(0.f, 0.f, 0.f, 0.f);
        if (gr < n) av = *(const float4*)(A + (size_t)gr * H + kk + acol4);
        As[acol4 + 0][arow] = av.x;
        As[acol4 + 1][arow] = av.y;
        As[acol4 + 2][arow] = av.z;
        As[acol4 + 3][arow] = av.w;

        if (tid < 128) {
            float4 wv = *(const float4*)(W + (size_t)(kk + wrow) * C + wcol4);
            *(float4*)&Bs[wrow][wcol4] = wv;
        }
        __syncthreads();

#pragma unroll
        for (int k = 0; k < 8; k++) {
            float4 a0 = *(const float4*)&As[k][ty * 8];
            float4 a1 = *(const float4*)&As[k][ty * 8 + 4];
            float4 bv = *(const float4*)&Bs[k][tx * 4];
            float a[8] = {a0.x, a0.y, a0.z, a0.w, a1.x, a1.y, a1.z, a1.w};
            float bb[4] = {bv.x, bv.y, bv.z, bv.w};
#pragma unroll
            for (int i = 0; i < 8; i++)
#pragma unroll
                for (int j = 0; j < 4; j++) acc[i][j] += a[i] * bb[j];
        }
        __syncthreads();
    }

#pragma unroll
    for (int i = 0; i < 8; i++) {
        int gr = block_row + ty * 8 + i;
        if (gr < n) {
            int cc = tx * 4;
            float4 v;
            v.x = acc[i][0] + b[cc + 0];
            v.y = acc[i][1] + b[cc + 1];
            v.z = acc[i][2] + b[cc + 2];
            v.w = acc[i][3] + b[cc + 3];
            *(float4*)(out + (size_t)gr * C + cc) = v;
        }
    }
}

// ---------------------------------------------------------------------------
// In-place row-wise log_softmax over C=64. One warp per row.
// ---------------------------------------------------------------------------
__global__ void __launch_bounds__(128) lsm_kernel(float* __restrict__ out, int n) {
    int r = blockIdx.x * 4 + (threadIdx.x >> 5);
    if (r >= n) return;
    int lane = threadIdx.x & 31;
    float* row = out + (size_t)r * C;
    float a = row[lane];
    float b = row[lane + 32];
    float m = fmaxf(a, b);
#pragma unroll
    for (int o = 16; o > 0; o >>= 1) m = fmaxf(m, __shfl_xor_sync(0xffffffffu, m, o));
    float s = expf(a - m) + expf(b - m);
#pragma unroll
    for (int o = 16; o > 0; o >>= 1) s += __shfl_xor_sync(0xffffffffu, s, o);
    float lg = m + logf(s);
    row[lane]      = a - lg;
    row[lane + 32] = b - lg;
}

// ---------------------------------------------------------------------------
extern "C" void kernel_launch(void* const* d_in, const int* in_sizes, int n_in,
                              void* d_out, int out_size) {
    const float* x      = (const float*)d_in[0];
    const int*   ei     = (const int*)  d_in[1];
    // d_in[2] = edge_attr (ignored by GIN)
    const float* conv_w = (const float*)d_in[3];
    const float* conv_b = (const float*)d_in[4];
    const float* bn_g   = (const float*)d_in[5];
    const float* bn_b   = (const float*)d_in[6];
    const float* bn_m   = (const float*)d_in[7];
    const float* bn_v   = (const float*)d_in[8];
    const float* fc_w   = (const float*)d_in[9];
    const float* fc_b   = (const float*)d_in[10];

    const int n  = in_sizes[0] / H;
    const int nE = in_sizes[1] / 2;
    const int* src = ei;
    const int* dst = ei + nE;

    float *hA, *hB, *sc, *bi;
    cudaGetSymbolAddress((void**)&hA, g_hA);
    cudaGetSymbolAddress((void**)&hB, g_hB);
    cudaGetSymbolAddress((void**)&sc, g_scale);
    cudaGetSymbolAddress((void**)&bi, g_bias);

    // enable >48KB dynamic smem for the fused MLP (idempotent, not a stream op)
    static int smem_set = 0;
    if (!smem_set) {
        cudaFuncSetAttribute(mlp3_tc_kernel,
                             cudaFuncAttributeMaxDynamicSharedMemorySize, MLP3_SMEM);
        smem_set = 1;
    }

    setup_kernel<<<3, 256>>>(conv_b, bn_g, bn_b, bn_m, bn_v);

    // ---- CSR build (once per launch; reused by both convs) ----
    const int nb = (n + 1023) / 1024;
    zero_kernel<<<(n + 255) / 256, 256>>>(n);
    hist_kernel<<<(nE + 255) / 256, 256>>>(dst, nE);
    scanA_kernel<<<nb, 1024>>>(n);
    scanB_kernel<<<1, 32>>>(nb);
    scanC_kernel<<<nb, 1024>>>(n);
    fill_kernel<<<(nE + 255) / 256, 256>>>(src, dst, nE);

    const int gblocks = (n * 32 + 255) / 256;   // one warp per node
    const int mblocks = (n + 127) / 128;

    // ---- GIN conv 1: gather + fused 3-layer MLP ----
    gather_kernel<<<gblocks, 256>>>(x, hB, n);
    mlp3_tc_kernel<<<mblocks, 256, MLP3_SMEM>>>(hB, conv_w, sc, bi, hA, n);

    // ---- GIN conv 2 ----
    gather_kernel<<<gblocks, 256>>>(hA, hB, n);
    mlp3_tc_kernel<<<mblocks, 256, MLP3_SMEM>>>(hB, conv_w + 3 * H * H,
                                                sc + 3 * H, bi + 3 * H, hA, n);

    // ---- FC + log_softmax ----
    fc_kernel<<<mblocks, 256>>>(hA, fc_w, fc_b, (float*)d_out, n);
    lsm_kernel<<<(n + 3) / 4, 128>>>((float*)d_out, n);
}